// round 1
// baseline (speedup 1.0000x reference)
#include <cuda_runtime.h>
#include <stdint.h>
#include <math.h>

#define NB 64
#define NC 512
#define HW 1024
#define NE 16
#define TABLE 65536   // 2048*32 per expert

// ---------------- scratch (allocation-free: __device__ globals) ----------------
__device__ float g_x[NB * NC];       // pooled activations
__device__ float g_route[NB * NE];   // pre-softmax router logits
__device__ float g_noise[NB * NE];   // noise logits
__device__ float g_w[NE];            // per-expert combine weights (already /B)

// ---------------- threefry2x32 (JAX-compatible) ----------------
__device__ __forceinline__ uint32_t rotl32(uint32_t x, int d) {
    return (x << d) | (x >> (32 - d));
}

__device__ __forceinline__ void threefry2x32(uint32_t k0, uint32_t k1,
                                             uint32_t x0, uint32_t x1,
                                             uint32_t* o0, uint32_t* o1) {
    const uint32_t ks0 = k0, ks1 = k1, ks2 = k0 ^ k1 ^ 0x1BD11BDAu;
    uint32_t a = x0 + ks0, b = x1 + ks1;
    const int r0[4] = {13, 15, 26, 6};
    const int r1[4] = {17, 29, 16, 24};
#define TF_ROUND4(R) \
    { a += b; b = rotl32(b, (R)[0]); b ^= a; \
      a += b; b = rotl32(b, (R)[1]); b ^= a; \
      a += b; b = rotl32(b, (R)[2]); b ^= a; \
      a += b; b = rotl32(b, (R)[3]); b ^= a; }
    TF_ROUND4(r0); a += ks1; b += ks2 + 1u;
    TF_ROUND4(r1); a += ks2; b += ks0 + 2u;
    TF_ROUND4(r0); a += ks0; b += ks1 + 3u;
    TF_ROUND4(r1); a += ks1; b += ks2 + 4u;
    TF_ROUND4(r0); a += ks2; b += ks0 + 5u;
#undef TF_ROUND4
    *o0 = a; *o1 = b;
}

// eps[j] for flat j in [0, 1024): jax.random.normal(key(42), (64,16))
// counts = iota(1024), split as x0=j (j<512) pairs with x1=j+512.
__device__ __forceinline__ float jax_normal_eps(int j) {
    uint32_t o0, o1, bits;
    if (j < 512) {
        threefry2x32(0u, 42u, (uint32_t)j, (uint32_t)(j + 512), &o0, &o1);
        bits = o0;
    } else {
        threefry2x32(0u, 42u, (uint32_t)(j - 512), (uint32_t)j, &o0, &o1);
        bits = o1;
    }
    float f = __uint_as_float((bits >> 9) | 0x3f800000u) - 1.0f;   // [0,1)
    const float lo = __uint_as_float(0xBF7FFFFFu);                 // nextafter(-1,0)
    // hi - lo rounds to exactly 2.0f in float32 (as XLA computes it)
    float u = fmaxf(lo, f * 2.0f + lo);
    return 1.4142135623730951f * erfinvf(u);
}

__device__ __forceinline__ float softplus_f(float x) {
    // jax.nn.softplus = logaddexp(x, 0) = max(x,0) + log1p(exp(-|x|))
    return fmaxf(x, 0.0f) + log1pf(expf(-fabsf(x)));
}

// ---------------- Kernel A: mean pool over H*W (one warp per (b,c) row) ----------------
__global__ void k_pool(const float* __restrict__ in) {
    int warp = (blockIdx.x * blockDim.x + threadIdx.x) >> 5;
    int lane = threadIdx.x & 31;
    if (warp >= NB * NC) return;
    const float4* p = (const float4*)(in + (size_t)warp * HW);
    float s = 0.0f;
#pragma unroll
    for (int i = 0; i < 8; i++) {
        float4 v = p[lane + i * 32];
        s += (v.x + v.y) + (v.z + v.w);
    }
#pragma unroll
    for (int o = 16; o > 0; o >>= 1) s += __shfl_down_sync(0xffffffffu, s, o);
    if (lane == 0) g_x[warp] = s * (1.0f / 1024.0f);
}

// ---------------- Kernel B: fused dual GEMV (route + noise logits), block per batch ----------------
__global__ void k_gemv(const float* __restrict__ Wr, const float* __restrict__ br,
                       const float* __restrict__ Wn, const float* __restrict__ bn) {
    __shared__ float xs[NC];
    int b = blockIdx.x;
    for (int i = threadIdx.x; i < NC; i += blockDim.x) xs[i] = g_x[b * NC + i];
    __syncthreads();
    int warp = threadIdx.x >> 5, lane = threadIdx.x & 31;
#pragma unroll
    for (int t = 0; t < 2; t++) {
        int e = warp * 2 + t;
        float sr = 0.0f, sn = 0.0f;
        for (int c = lane; c < NC; c += 32) {
            float xv = xs[c];
            sr = fmaf(xv, __ldg(&Wr[c * NE + e]), sr);
            sn = fmaf(xv, __ldg(&Wn[c * NE + e]), sn);
        }
#pragma unroll
        for (int o = 16; o > 0; o >>= 1) {
            sr += __shfl_down_sync(0xffffffffu, sr, o);
            sn += __shfl_down_sync(0xffffffffu, sn, o);
        }
        if (lane == 0) {
            g_route[b * NE + e] = sr + __ldg(&br[e]);
            g_noise[b * NE + e] = sn + __ldg(&bn[e]);
        }
    }
}

// ---------------- Kernel C: router (softmax, noise, top-2, weights, z-loss), 1 block ----------------
__global__ void k_router(float* __restrict__ zloss_out) {
    __shared__ float ws[NE];
    __shared__ float zsum;
    int t = threadIdx.x;
    if (t < NE) ws[t] = 0.0f;
    if (t == 0) zsum = 0.0f;
    __syncthreads();

    if (t < NB) {
        float lg[NE], nz[NE];
#pragma unroll
        for (int e = 0; e < NE; e++) {
            lg[e] = g_route[t * NE + e];
            nz[e] = g_noise[t * NE + e];
        }
        // softmax(logits)
        float m = -INFINITY;
#pragma unroll
        for (int e = 0; e < NE; e++) m = fmaxf(m, lg[e]);
        float s = 0.0f;
#pragma unroll
        for (int e = 0; e < NE; e++) { lg[e] = expf(lg[e] - m); s += lg[e]; }
        float inv = 1.0f / s;
#pragma unroll
        for (int e = 0; e < NE; e++) lg[e] *= inv;

        // noise = softmax(eps * softplus(noise_logits))
        float pre[NE];
        float m2 = -INFINITY;
#pragma unroll
        for (int e = 0; e < NE; e++) {
            float eps = jax_normal_eps(t * NE + e);
            pre[e] = eps * softplus_f(nz[e]);
            m2 = fmaxf(m2, pre[e]);
        }
        float s2 = 0.0f;
#pragma unroll
        for (int e = 0; e < NE; e++) { pre[e] = expf(pre[e] - m2); s2 += pre[e]; }
        float inv2 = 1.0f / s2;

        // noisy logits
        float ny[NE];
#pragma unroll
        for (int e = 0; e < NE; e++) ny[e] = lg[e] + pre[e] * inv2;

        // z-loss: logsumexp^2
        float mm = -INFINITY;
#pragma unroll
        for (int e = 0; e < NE; e++) mm = fmaxf(mm, ny[e]);
        float ss = 0.0f;
#pragma unroll
        for (int e = 0; e < NE; e++) ss += expf(ny[e] - mm);
        float lse = mm + logf(ss);
        atomicAdd(&zsum, lse * lse);

        // top-2 (first occurrence wins ties, matching lax.top_k)
        int i0 = 0;
        float v0 = ny[0];
#pragma unroll
        for (int e = 1; e < NE; e++) if (ny[e] > v0) { v0 = ny[e]; i0 = e; }
        int i1 = -1;
        float v1 = -INFINITY;
#pragma unroll
        for (int e = 0; e < NE; e++) if (e != i0 && ny[e] > v1) { v1 = ny[e]; i1 = e; }

        // softmax over [v0, v1]
        float r1e = expf(v1 - v0);
        float rinv = 1.0f / (1.0f + r1e);
        atomicAdd(&ws[i0], rinv);
        atomicAdd(&ws[i1], r1e * rinv);
    }
    __syncthreads();
    if (t < NE) g_w[t] = ws[t] * (1.0f / (float)NB);
    if (t == 0) *zloss_out = zsum * (1.0f / (float)NB);
}

// ---------------- Kernel D: combined = sum_e w[e] * A_logs[e] ----------------
__global__ void k_combine(const float* __restrict__ A, float* __restrict__ out) {
    int i = blockIdx.x * blockDim.x + threadIdx.x;
    if (i >= TABLE) return;
    float s = 0.0f;
#pragma unroll
    for (int e = 0; e < NE; e++)
        s = fmaf(g_w[e], __ldg(&A[(size_t)e * TABLE + i]), s);
    out[i] = s;
}

// ---------------- launch ----------------
extern "C" void kernel_launch(void* const* d_in, const int* in_sizes, int n_in,
                              void* d_out, int out_size) {
    const float* inputs  = (const float*)d_in[0];  // [64,512,32,32]
    const float* W_route = (const float*)d_in[1];  // [512,16]
    const float* b_route = (const float*)d_in[2];  // [16]
    const float* W_noise = (const float*)d_in[3];  // [512,16]
    const float* b_noise = (const float*)d_in[4];  // [16]
    const float* A_logs  = (const float*)d_in[5];  // [16,2048,32]
    float* out = (float*)d_out;

    // A: 32768 rows, one warp each; 8 warps/block -> 4096 blocks
    k_pool<<<(NB * NC) / 8, 256>>>(inputs);
    // B: one block per batch row
    k_gemv<<<NB, 256>>>(W_route, b_route, W_noise, b_noise);
    // C: single block; writes weights + z_loss (last output element)
    k_router<<<1, 64>>>(out + (out_size - 1));
    // D: combined table
    k_combine<<<(TABLE + 255) / 256, 256>>>(A_logs, out);
}

// round 2
// speedup vs baseline: 1.2869x; 1.2869x over previous
#include <cuda_runtime.h>
#include <stdint.h>
#include <math.h>

#define NB 64
#define NC 512
#define HW 1024
#define NE 16
#define TABLE 65536   // 2048*32 per expert

// ---------------- scratch (allocation-free: __device__ globals) ----------------
__device__ float g_x[NB * NC];     // pooled activations
__device__ int   g_i0[NB];         // top-1 expert per batch
__device__ int   g_i1[NB];         // top-2 expert per batch
__device__ float g_p0[NB];         // top-1 prob
__device__ float g_p1[NB];         // top-2 prob
__device__ float g_z[NB];          // lse^2 per batch

// ---------------- threefry2x32 (JAX-compatible) ----------------
__device__ __forceinline__ uint32_t rotl32(uint32_t x, int d) {
    return (x << d) | (x >> (32 - d));
}

__device__ __forceinline__ void threefry2x32(uint32_t k0, uint32_t k1,
                                             uint32_t x0, uint32_t x1,
                                             uint32_t* o0, uint32_t* o1) {
    const uint32_t ks0 = k0, ks1 = k1, ks2 = k0 ^ k1 ^ 0x1BD11BDAu;
    uint32_t a = x0 + ks0, b = x1 + ks1;
    const int r0[4] = {13, 15, 26, 6};
    const int r1[4] = {17, 29, 16, 24};
#define TF_ROUND4(R) \
    { a += b; b = rotl32(b, (R)[0]); b ^= a; \
      a += b; b = rotl32(b, (R)[1]); b ^= a; \
      a += b; b = rotl32(b, (R)[2]); b ^= a; \
      a += b; b = rotl32(b, (R)[3]); b ^= a; }
    TF_ROUND4(r0); a += ks1; b += ks2 + 1u;
    TF_ROUND4(r1); a += ks2; b += ks0 + 2u;
    TF_ROUND4(r0); a += ks0; b += ks1 + 3u;
    TF_ROUND4(r1); a += ks1; b += ks2 + 4u;
    TF_ROUND4(r0); a += ks2; b += ks0 + 5u;
#undef TF_ROUND4
    *o0 = a; *o1 = b;
}

// eps[j] for flat j in [0, 1024): jax.random.normal(key(42), (64,16))
__device__ __forceinline__ float jax_normal_eps(int j) {
    uint32_t o0, o1, bits;
    if (j < 512) {
        threefry2x32(0u, 42u, (uint32_t)j, (uint32_t)(j + 512), &o0, &o1);
        bits = o0;
    } else {
        threefry2x32(0u, 42u, (uint32_t)(j - 512), (uint32_t)j, &o0, &o1);
        bits = o1;
    }
    float f = __uint_as_float((bits >> 9) | 0x3f800000u) - 1.0f;   // [0,1)
    const float lo = __uint_as_float(0xBF7FFFFFu);                 // nextafter(-1,0)
    float u = fmaxf(lo, f * 2.0f + lo);                            // hi-lo == 2.0f
    return 1.4142135623730951f * erfinvf(u);
}

__device__ __forceinline__ float softplus_f(float x) {
    return fmaxf(x, 0.0f) + log1pf(expf(-fabsf(x)));
}

// ---------------- Kernel A: mean pool over H*W (one warp per (b,c) row) ----------------
__global__ void k_pool(const float* __restrict__ in) {
    int warp = (blockIdx.x * blockDim.x + threadIdx.x) >> 5;
    int lane = threadIdx.x & 31;
    const float4* p = (const float4*)(in + (size_t)warp * HW);
    float s = 0.0f;
#pragma unroll
    for (int i = 0; i < 8; i++) {
        float4 v = __ldcs(&p[lane + i * 32]);
        s += (v.x + v.y) + (v.z + v.w);
    }
#pragma unroll
    for (int o = 16; o > 0; o >>= 1) s += __shfl_down_sync(0xffffffffu, s, o);
    if (lane == 0) g_x[warp] = s * (1.0f / 1024.0f);
}

// ---------------- Kernel B: fused dual GEMV + per-batch router, block per batch ----------------
__global__ void k_gemv_router(const float* __restrict__ Wr, const float* __restrict__ br,
                              const float* __restrict__ Wn, const float* __restrict__ bn) {
    __shared__ float xs[NC];
    __shared__ float sr_s[NE], sn_s[NE];
    int b = blockIdx.x;
    for (int i = threadIdx.x; i < NC; i += blockDim.x) xs[i] = g_x[b * NC + i];
    __syncthreads();
    int warp = threadIdx.x >> 5, lane = threadIdx.x & 31;
#pragma unroll
    for (int t = 0; t < 2; t++) {
        int e = warp * 2 + t;
        float sr = 0.0f, sn = 0.0f;
        for (int c = lane; c < NC; c += 32) {
            float xv = xs[c];
            sr = fmaf(xv, __ldg(&Wr[c * NE + e]), sr);
            sn = fmaf(xv, __ldg(&Wn[c * NE + e]), sn);
        }
#pragma unroll
        for (int o = 16; o > 0; o >>= 1) {
            sr += __shfl_down_sync(0xffffffffu, sr, o);
            sn += __shfl_down_sync(0xffffffffu, sn, o);
        }
        if (lane == 0) {
            sr_s[e] = sr + __ldg(&br[e]);
            sn_s[e] = sn + __ldg(&bn[e]);
        }
    }
    __syncthreads();

    // Router math: warp 0, lanes 0..15 carry one expert each (lanes 16-31 neutral)
    if (warp == 0) {
        bool act = lane < NE;
        float lg = act ? sr_s[lane] : -INFINITY;
        float nz = act ? sn_s[lane] : 0.0f;

        // softmax(route logits)
        float m = lg;
#pragma unroll
        for (int o = 16; o > 0; o >>= 1) m = fmaxf(m, __shfl_xor_sync(0xffffffffu, m, o));
        float el = act ? expf(lg - m) : 0.0f;
        float s = el;
#pragma unroll
        for (int o = 16; o > 0; o >>= 1) s += __shfl_xor_sync(0xffffffffu, s, o);
        float soft = el / s;

        // noise = softmax(eps * softplus(noise_logits))
        float pre = -INFINITY;
        if (act) {
            float eps = jax_normal_eps(b * NE + lane);
            pre = eps * softplus_f(nz);
        }
        float m2 = pre;
#pragma unroll
        for (int o = 16; o > 0; o >>= 1) m2 = fmaxf(m2, __shfl_xor_sync(0xffffffffu, m2, o));
        float ep = act ? expf(pre - m2) : 0.0f;
        float s2 = ep;
#pragma unroll
        for (int o = 16; o > 0; o >>= 1) s2 += __shfl_xor_sync(0xffffffffu, s2, o);

        // noisy logits
        float ny = act ? (soft + ep / s2) : -INFINITY;

        // argmax #1 (ties -> lower index, matching lax.top_k)
        float v0 = ny; int i0 = lane;
#pragma unroll
        for (int o = 16; o > 0; o >>= 1) {
            float vo = __shfl_xor_sync(0xffffffffu, v0, o);
            int io = __shfl_xor_sync(0xffffffffu, i0, o);
            if (vo > v0 || (vo == v0 && io < i0)) { v0 = vo; i0 = io; }
        }
        // argmax #2 (exclude i0)
        float v1 = (lane == i0) ? -INFINITY : ny; int i1 = lane;
#pragma unroll
        for (int o = 16; o > 0; o >>= 1) {
            float vo = __shfl_xor_sync(0xffffffffu, v1, o);
            int io = __shfl_xor_sync(0xffffffffu, i1, o);
            if (vo > v1 || (vo == v1 && io < i1)) { v1 = vo; i1 = io; }
        }

        // logsumexp over noisy logits (v0 is the max)
        float ee = act ? expf(ny - v0) : 0.0f;
        float ss = ee;
#pragma unroll
        for (int o = 16; o > 0; o >>= 1) ss += __shfl_xor_sync(0xffffffffu, ss, o);

        if (lane == 0) {
            float lse = v0 + logf(ss);
            float e1 = expf(v1 - v0);
            float p0 = 1.0f / (1.0f + e1);
            g_i0[b] = i0; g_i1[b] = i1;
            g_p0[b] = p0; g_p1[b] = e1 * p0;
            g_z[b]  = lse * lse;
        }
    }
}

// ---------------- Kernel C: combined = sum_e w[e]*A[e] (+ z-loss from block 0) ----------------
__global__ void k_combine(const float* __restrict__ A, float* __restrict__ out) {
    __shared__ int   si0[NB], si1[NB];
    __shared__ float sp0[NB], sp1[NB];
    __shared__ float ws[NE];
    int t = threadIdx.x;
    if (t < NB) {
        si0[t] = g_i0[t]; si1[t] = g_i1[t];
        sp0[t] = g_p0[t]; sp1[t] = g_p1[t];
    }
    __syncthreads();
    if (t < NE) {
        float w = 0.0f;
#pragma unroll 8
        for (int b = 0; b < NB; b++) {
            if (si0[b] == t) w += sp0[b];
            if (si1[b] == t) w += sp1[b];
        }
        ws[t] = w * (1.0f / (float)NB);
    }
    if (blockIdx.x == 0 && t == 64) {
        float z = 0.0f;
#pragma unroll
        for (int b = 0; b < NB; b++) z += g_z[b];
        out[TABLE] = z * (1.0f / (float)NB);
    }
    __syncthreads();

    int idx = blockIdx.x * blockDim.x + t;   // float4 index, 16384 total
    const float4* A4 = (const float4*)A;
    float4 acc = make_float4(0.f, 0.f, 0.f, 0.f);
#pragma unroll
    for (int e = 0; e < NE; e++) {
        float4 v = __ldg(&A4[(size_t)e * (TABLE / 4) + idx]);
        float w = ws[e];
        acc.x = fmaf(w, v.x, acc.x);
        acc.y = fmaf(w, v.y, acc.y);
        acc.z = fmaf(w, v.z, acc.z);
        acc.w = fmaf(w, v.w, acc.w);
    }
    ((float4*)out)[idx] = acc;
}

// ---------------- launch ----------------
extern "C" void kernel_launch(void* const* d_in, const int* in_sizes, int n_in,
                              void* d_out, int out_size) {
    const float* inputs  = (const float*)d_in[0];  // [64,512,32,32]
    const float* W_route = (const float*)d_in[1];  // [512,16]
    const float* b_route = (const float*)d_in[2];  // [16]
    const float* W_noise = (const float*)d_in[3];  // [512,16]
    const float* b_noise = (const float*)d_in[4];  // [16]
    const float* A_logs  = (const float*)d_in[5];  // [16,2048,32]
    float* out = (float*)d_out;

    k_pool<<<(NB * NC) / 8, 256>>>(inputs);
    k_gemv_router<<<NB, 256>>>(W_route, b_route, W_noise, b_noise);
    k_combine<<<(TABLE / 4) / 128, 128>>>(A_logs, out);
}